// round 12
// baseline (speedup 1.0000x reference)
#include <cuda_runtime.h>

// Problem constants (fixed by the dataset)
#define B_   128
#define D_   512
#define KP_  2048        // K + num_positive
#define NF_  16084
#define NP_  604731
#define INV_T 14.2857142857142857f   // 1 / 0.07

#define NCHUNK 8                      // loss chunks per batch element
#define ROWS_PER_CHUNK (2 * KP_ / NCHUNK)   // 512 rows per chunk

#define COPY_BLKS_1 52
#define COPY_BLKS_2 1996
#define COPY_BLKS   (COPY_BLKS_1 + COPY_BLKS_2)   // 2048
#define LOSS_BLKS   (B_ * NCHUNK)                 // 1024
#define TOTAL_BLKS  (COPY_BLKS + LOSS_BLKS)       // 3072

// Deterministic scratch (no float atomics anywhere)
__device__ float g_m1[B_][NCHUNK], g_s1[B_][NCHUNK];
__device__ float g_m2[B_][NCHUNK], g_s2[B_][NCHUNK];
__device__ float g_pos[B_][4];   // logits at k=0 (t0,t1) and k=KP (t0,t1)

// ---------------------------------------------------------------------------
// Copy span, fully vectorized despite the 4B dst misalignment.
// dst = out+1(+mult of 4) -> first 16B-aligned dst element is j = 3.
// Chunk v covers dst elements [3+4v, 7+4v) = src elements [3+4v, 7+4v),
// served by TWO aligned LDG.128 (srcv[v] gives 4v+3 = .w; srcv[v+1] gives
// 4v+4..4v+6 = .xyz) and ONE aligned STG.128. 3 instructions per 16B
// (vs 5 with scalar loads); the overlapping srcv[v+1] is the neighbor
// lane's srcv[v] -> L1 hit, no extra DRAM traffic. 4x grid-stride unroll
// keeps 8 LDG.128 (128B) per thread in flight.
// srcv[nv] is in-bounds for both banks (4*nv+3 == n-1), so no guard needed.
// SRC_CACHE: 0 = streaming loads (.cs), 1 = cached (warm L2 for gathers).
// Stores always streaming (write-once traffic).
// ---------------------------------------------------------------------------
template<int SRC_CACHE>
__device__ __forceinline__ void copy_span(const float* __restrict__ src,
                                          float* __restrict__ dst,
                                          long long n,
                                          long long tid0, long long stride)
{
    const long long PRO = 3;
    const long long nv = (n - PRO) >> 2;
    const float4* __restrict__ srcv = (const float4*)src;   // 16B aligned
    float4* __restrict__ dstv = (float4*)(dst + PRO);       // 16B aligned

    if (tid0 < PRO) dst[tid0] = src[tid0];

#define LDV(P) (SRC_CACHE ? *(P) : __ldcs(P))

    long long v = tid0;
    for (; v + 3 * stride < nv; v += 4 * stride) {
        float4 A[4], Bv[4];
#pragma unroll
        for (int u = 0; u < 4; u++) {
            const long long c = v + u * stride;
            A[u]  = LDV(srcv + c);
            Bv[u] = LDV(srcv + c + 1);
        }
#pragma unroll
        for (int u = 0; u < 4; u++) {
            const long long c = v + u * stride;
            float4 st = {A[u].w, Bv[u].x, Bv[u].y, Bv[u].z};
            __stcs(dstv + c, st);
        }
    }
    for (; v < nv; v += stride) {
        float4 A  = LDV(srcv + v);
        float4 Bv = LDV(srcv + v + 1);
        float4 st = {A.w, Bv.x, Bv.y, Bv.z};
        __stcs(dstv + v, st);
    }
#undef LDV

    const long long tail = PRO + 4 * nv;
    const long long t = tail + tid0;
    if (t < n) dst[t] = src[t];
}

// ---------------------------------------------------------------------------
// Loss chunk body (templated on bank residency).
// 16 warps; warp w handles rows r = 2*w + 32*i (+1) of the chunk's 512 rows.
// Lanes keep v1[b]/v2[b] in registers; per iteration 8 independent LDG.128 +
// 64 FFMA + 4 interleaved butterfly chains, then online-softmax updates.
// ---------------------------------------------------------------------------
template<int STREAMROW>
__device__ __forceinline__ float4 ld_row(const float* p)
{
    if (STREAMROW) return __ldcs((const float4*)p);
    return *(const float4*)p;
}

template<int STREAMROW>
__device__ __forceinline__ void loss_chunk(const float* __restrict__ mem,
                                           const int*   __restrict__ idx,
                                           const float4 rv1[4], const float4 rv2[4],
                                           int warp, int lane,
                                           float& m1, float& s1,
                                           float& m2, float& s2,
                                           int b, int chunk)
{
    const int NW = 16;
#pragma unroll 1
    for (int r = 2 * warp; r < ROWS_PER_CHUNK; r += 2 * NW) {
        const float* __restrict__ rowA = mem + (size_t)__ldg(idx + r)     * D_;
        const float* __restrict__ rowB = mem + (size_t)__ldg(idx + r + 1) * D_;

        float a1 = 0.0f, a2 = 0.0f, c1 = 0.0f, c2 = 0.0f;
#pragma unroll
        for (int c = 0; c < 4; c++) {
            float4 wa = ld_row<STREAMROW>(rowA + 128 * c + 4 * lane);
            float4 wb = ld_row<STREAMROW>(rowB + 128 * c + 4 * lane);
            a1 += wa.x * rv1[c].x + wa.y * rv1[c].y + wa.z * rv1[c].z + wa.w * rv1[c].w;
            a2 += wa.x * rv2[c].x + wa.y * rv2[c].y + wa.z * rv2[c].z + wa.w * rv2[c].w;
            c1 += wb.x * rv1[c].x + wb.y * rv1[c].y + wb.z * rv1[c].z + wb.w * rv1[c].w;
            c2 += wb.x * rv2[c].x + wb.y * rv2[c].y + wb.z * rv2[c].z + wb.w * rv2[c].w;
        }
#pragma unroll
        for (int off = 16; off; off >>= 1) {
            a1 += __shfl_xor_sync(0xffffffffu, a1, off);
            a2 += __shfl_xor_sync(0xffffffffu, a2, off);
            c1 += __shfl_xor_sync(0xffffffffu, c1, off);
            c2 += __shfl_xor_sync(0xffffffffu, c2, off);
        }
        a1 *= INV_T; a2 *= INV_T; c1 *= INV_T; c2 *= INV_T;

        // positive logits: global k==0 -> chunk0,r==0; k==KP -> chunk4,r==0
        if (lane == 0 && r == 0 && (chunk == 0 || chunk == NCHUNK / 2)) {
            const int o = (chunk == 0) ? 0 : 2;
            g_pos[b][o + 0] = a1;
            g_pos[b][o + 1] = a2;
        }

        float nm = fmaxf(m1, fmaxf(a1, c1));
        s1 = s1 * __expf(m1 - nm) + __expf(a1 - nm) + __expf(c1 - nm);
        m1 = nm;
        nm = fmaxf(m2, fmaxf(a2, c2));
        s2 = s2 * __expf(m2 - nm) + __expf(a2 - nm) + __expf(c2 - nm);
        m2 = nm;
    }
}

// ---------------------------------------------------------------------------
// Fused kernel. Roles INTERLEAVED by block id so every scheduling wave
// carries ~2/3 copy + 1/3 loss work (true overlap at 1 block/SM):
//   blk % 3 == 1 -> loss block, loss_id = blk / 3          (1024 blocks)
//   otherwise    -> copy block, copy_id = blk - (blk+2)/3  (2048 blocks)
// ---------------------------------------------------------------------------
__global__ void __launch_bounds__(512) fused_kernel(const float* __restrict__ v1,
                                                    const float* __restrict__ v2,
                                                    const int*   __restrict__ idx1,
                                                    const int*   __restrict__ idx2,
                                                    const float* __restrict__ mem1,
                                                    const float* __restrict__ mem2,
                                                    float* __restrict__ out)
{
    const int blk = blockIdx.x;
    const bool is_loss = (blk % 3 == 1) && (blk / 3 < LOSS_BLKS);

    // ---------------- copy part ----------------
    if (!is_loss) {
        const int cid = blk - (blk + 2) / 3;     // 0..COPY_BLKS-1
        const long long N1 = (long long)NF_ * D_;
        const long long N2 = (long long)NP_ * D_;
        if (cid < COPY_BLKS_1) {
            const long long stride = (long long)COPY_BLKS_1 * 512;
            const long long tid0 = (long long)cid * 512 + threadIdx.x;
            copy_span<1>(mem1, out + 1, N1, tid0, stride);     // cached: warm L2
        } else {
            const long long stride = (long long)COPY_BLKS_2 * 512;
            const long long tid0 = (long long)(cid - COPY_BLKS_1) * 512 + threadIdx.x;
            copy_span<0>(mem2, out + 1 + N1, N2, tid0, stride); // streaming
        }
        return;
    }

    // ---------------- loss partial part ----------------
    const int l     = blk / 3;       // 0..1023
    const int b     = l >> 3;        // / NCHUNK
    const int chunk = l & 7;         // % NCHUNK
    const int tid   = threadIdx.x;
    const int warp  = tid >> 5;
    const int lane  = tid & 31;
    const int NW    = 16;

    __shared__ float sm_m1[NW], sm_s1[NW], sm_m2[NW], sm_s2[NW];

    // v1[b], v2[b] into registers: lane covers d = 128*c + 4*lane + {0..3}
    float4 rv1[4], rv2[4];
#pragma unroll
    for (int c = 0; c < 4; c++) {
        rv1[c] = *(const float4*)(v1 + (size_t)b * D_ + 128 * c + 4 * lane);
        rv2[c] = *(const float4*)(v2 + (size_t)b * D_ + 128 * c + 4 * lane);
    }

    // chunk -> bank and local index base
    const int kbase = chunk * ROWS_PER_CHUNK;          // global k of chunk start
    const bool bank2 = (kbase >= KP_);

    float m1 = -1e30f, s1 = 0.0f;
    float m2 = -1e30f, s2 = 0.0f;

    if (bank2) {
        const int* __restrict__ idx = idx2 + b * KP_ + (kbase - KP_);
        loss_chunk<1>(mem2, idx, rv1, rv2, warp, lane, m1, s1, m2, s2, b, chunk);
    } else {
        const int* __restrict__ idx = idx1 + b * KP_ + kbase;
        loss_chunk<0>(mem1, idx, rv1, rv2, warp, lane, m1, s1, m2, s2, b, chunk);
    }

    if (lane == 0) {
        sm_m1[warp] = m1; sm_s1[warp] = s1;
        sm_m2[warp] = m2; sm_s2[warp] = s2;
    }
    __syncthreads();

    if (tid == 0) {
        float M1 = -1e30f, M2 = -1e30f;
#pragma unroll
        for (int w = 0; w < NW; w++) {
            M1 = fmaxf(M1, sm_m1[w]);
            M2 = fmaxf(M2, sm_m2[w]);
        }
        float S1 = 0.0f, S2 = 0.0f;
#pragma unroll
        for (int w = 0; w < NW; w++) {
            S1 += sm_s1[w] * expf(sm_m1[w] - M1);
            S2 += sm_s2[w] * expf(sm_m2[w] - M2);
        }
        g_m1[b][chunk] = M1; g_s1[b][chunk] = S1;
        g_m2[b][chunk] = M2; g_s2[b][chunk] = S2;
    }
}

// ---------------------------------------------------------------------------
// Kernel 2: momentum row updates (blocks 0..2B-1) + loss finalize (block 2B).
// Duplicate labels: scatter "last update wins".
// ---------------------------------------------------------------------------
__global__ void __launch_bounds__(128) update_kernel(const float* __restrict__ v1,
                                                     const int*   __restrict__ y1,
                                                     const float* __restrict__ v2,
                                                     const int*   __restrict__ y2,
                                                     const float* __restrict__ mem1,
                                                     const float* __restrict__ mem2,
                                                     float* __restrict__ out)
{
    const int blk = blockIdx.x;

    if (blk == 2 * B_) {  // ---- loss finalize: thread b merges chunks ----
        const int tid = threadIdx.x;   // 128 threads, one per b
        float contrib;
        {
            const int b = tid;
            float M1 = -1e30f, M2 = -1e30f;
#pragma unroll
            for (int j = 0; j < NCHUNK; j++) {
                M1 = fmaxf(M1, g_m1[b][j]);
                M2 = fmaxf(M2, g_m2[b][j]);
            }
            float S1 = 0.0f, S2 = 0.0f;
#pragma unroll
            for (int j = 0; j < NCHUNK; j++) {
                S1 += g_s1[b][j] * expf(g_m1[b][j] - M1);
                S2 += g_s2[b][j] * expf(g_m2[b][j] - M2);
            }
            float lse1 = M1 + logf(S1);
            float lse2 = M2 + logf(S2);
            contrib = 0.5f * (g_pos[b][0] + g_pos[b][2]) - lse1
                    + 0.5f * (g_pos[b][1] + g_pos[b][3]) - lse2;
        }
        __shared__ float red[128];
        red[tid] = contrib;
        __syncthreads();
#pragma unroll
        for (int s = 64; s; s >>= 1) {
            if (tid < s) red[tid] += red[tid + s];
            __syncthreads();
        }
        if (tid == 0) out[0] = -red[0] / (2.0f * B_);
        return;
    }

    const int bank = blk / B_;   // 0 -> mem1, 1 -> mem2
    const int b    = blk % B_;

    const int*   __restrict__ y   = bank ? y2 : y1;
    const float* __restrict__ v   = bank ? v2 : v1;
    const float* __restrict__ mem = bank ? mem2 : mem1;
    float* __restrict__ dst = out + 1 + (bank ? (size_t)NF_ * D_ : (size_t)0);

    const int row = __ldg(y + b);
    // last-occurrence-wins: skip if a later b' writes the same row
    for (int b2 = b + 1; b2 < B_; b2++)
        if (__ldg(y + b2) == row) return;   // uniform across block

    const int tid = threadIdx.x;
    float p[4];
    float ss = 0.0f;
#pragma unroll
    for (int j = 0; j < 4; j++) {
        int d = tid + j * 128;
        float x = 0.5f * __ldg(mem + (size_t)row * D_ + d)
                + 0.5f * __ldg(v + (size_t)b * D_ + d);
        p[j] = x;
        ss += x * x;
    }
#pragma unroll
    for (int off = 16; off; off >>= 1)
        ss += __shfl_xor_sync(0xffffffffu, ss, off);

    __shared__ float wsum[4];
    if ((tid & 31) == 0) wsum[tid >> 5] = ss;
    __syncthreads();
    float tot = wsum[0] + wsum[1] + wsum[2] + wsum[3];
    float inv = 1.0f / sqrtf(tot);

#pragma unroll
    for (int j = 0; j < 4; j++) {
        int d = tid + j * 128;
        dst[(size_t)row * D_ + d] = p[j] * inv;
    }
}

// ---------------------------------------------------------------------------
// Launch
// inputs: 0 v1(f32 B*D) 1 y1(i32 B) 2 v2 3 y2 4 idx1(i32 B*KP) 5 idx2
//         6 memory_v1(f32 NF*D) 7 memory_v2(f32 NP*D)
// output: [loss, new_mem_v1 (NF*D), new_mem_v2 (NP*D)]
// ---------------------------------------------------------------------------
extern "C" void kernel_launch(void* const* d_in, const int* in_sizes, int n_in,
                              void* d_out, int out_size)
{
    (void)in_sizes; (void)n_in; (void)out_size;
    const float* v1   = (const float*)d_in[0];
    const int*   y1   = (const int*)  d_in[1];
    const float* v2   = (const float*)d_in[2];
    const int*   y2   = (const int*)  d_in[3];
    const int*   idx1 = (const int*)  d_in[4];
    const int*   idx2 = (const int*)  d_in[5];
    const float* mem1 = (const float*)d_in[6];
    const float* mem2 = (const float*)d_in[7];
    float* out = (float*)d_out;

    fused_kernel<<<TOTAL_BLKS, 512>>>(v1, v2, idx1, idx2, mem1, mem2, out);
    update_kernel<<<2 * B_ + 1, 128>>>(v1, y1, v2, y2, mem1, mem2, out);
}

// round 13
// speedup vs baseline: 1.0515x; 1.0515x over previous
#include <cuda_runtime.h>

// Problem constants (fixed by the dataset)
#define B_   128
#define D_   512
#define KP_  2048        // K + num_positive
#define NF_  16084
#define NP_  604731
#define INV_T 14.2857142857142857f   // 1 / 0.07

#define NCHUNK 8                      // loss chunks per batch element
#define ROWS_PER_CHUNK (2 * KP_ / NCHUNK)   // 512 rows per chunk

#define TPB 256                       // threads per fused block (2 blocks/SM)
#define NW  (TPB / 32)                // 8 warps

#define COPY_BLKS_1 104
#define COPY_BLKS_2 3992
#define COPY_BLKS   (COPY_BLKS_1 + COPY_BLKS_2)   // 4096
#define LOSS_BLKS   (B_ * NCHUNK)                 // 1024
#define TOTAL_BLKS  (COPY_BLKS + LOSS_BLKS)       // 5120

// Deterministic scratch (no float atomics anywhere)
__device__ float g_m1[B_][NCHUNK], g_s1[B_][NCHUNK];
__device__ float g_m2[B_][NCHUNK], g_s2[B_][NCHUNK];
__device__ float g_pos[B_][4];   // logits at k=0 (t0,t1) and k=KP (t0,t1)

// ---------------------------------------------------------------------------
// Copy span (R8-proven scheme): dst is 4B off 16B alignment. Vectorize on the
// destination (thread covers 4 consecutive dst floats at j ≡ 3 mod 4 ->
// STG.128); the 4 loads per chunk are scalar but aggregate-coalesced, each
// 128B line read exactly once (no overlapped vector loads: with .cs they
// double-read DRAM -- measured R12 regression). 4x grid-stride unroll.
// SRC_CACHE: 0=streaming (.cs), 1=cached (warm L2 for mem1 gathers).
// Stores always streaming (write-once traffic).
// ---------------------------------------------------------------------------
template<int SRC_CACHE>
__device__ __forceinline__ void copy_span(const float* __restrict__ src,
                                          float* __restrict__ dst,
                                          long long n,
                                          long long tid0, long long stride)
{
    const long long PRO = 3;
    const long long nv = (n - PRO) >> 2;

    if (tid0 < PRO) dst[tid0] = src[tid0];

#define LD1(J,OFS) (SRC_CACHE ? src[(J)+(OFS)] : __ldcs(src + (J) + (OFS)))

    long long v = tid0;
    for (; v + 3 * stride < nv; v += 4 * stride) {
        const long long j0 = PRO + 4 * v;
        const long long j1 = PRO + 4 * (v + stride);
        const long long j2 = PRO + 4 * (v + 2 * stride);
        const long long j3 = PRO + 4 * (v + 3 * stride);
        float4 r0, r1, r2, r3;
        r0.x = LD1(j0,0); r0.y = LD1(j0,1); r0.z = LD1(j0,2); r0.w = LD1(j0,3);
        r1.x = LD1(j1,0); r1.y = LD1(j1,1); r1.z = LD1(j1,2); r1.w = LD1(j1,3);
        r2.x = LD1(j2,0); r2.y = LD1(j2,1); r2.z = LD1(j2,2); r2.w = LD1(j2,3);
        r3.x = LD1(j3,0); r3.y = LD1(j3,1); r3.z = LD1(j3,2); r3.w = LD1(j3,3);
        __stcs((float4*)(dst + j0), r0);
        __stcs((float4*)(dst + j1), r1);
        __stcs((float4*)(dst + j2), r2);
        __stcs((float4*)(dst + j3), r3);
    }
    for (; v < nv; v += stride) {
        const long long j = PRO + 4 * v;
        float4 r;
        r.x = LD1(j,0); r.y = LD1(j,1); r.z = LD1(j,2); r.w = LD1(j,3);
        __stcs((float4*)(dst + j), r);
    }
#undef LD1

    const long long tail = PRO + 4 * nv;
    const long long t = tail + tid0;
    if (t < n) dst[t] = src[t];
}

// ---------------------------------------------------------------------------
// Loss chunk body. NW=8 warps; warp w handles rows r = 2*w + 16*i (+1) of
// the chunk's 512 rows. Lanes keep v1[b]/v2[b] in registers; per iteration
// 8 independent LDG.128 + 64 FFMA + 4 interleaved butterfly chains, then
// online-softmax updates.
// ---------------------------------------------------------------------------
__device__ __forceinline__ void loss_chunk(const float* __restrict__ mem,
                                           const int*   __restrict__ idx,
                                           const float4 rv1[4], const float4 rv2[4],
                                           int warp, int lane,
                                           float& m1, float& s1,
                                           float& m2, float& s2,
                                           int b, int chunk)
{
#pragma unroll 1
    for (int r = 2 * warp; r < ROWS_PER_CHUNK; r += 2 * NW) {
        const float* __restrict__ rowA = mem + (size_t)__ldg(idx + r)     * D_;
        const float* __restrict__ rowB = mem + (size_t)__ldg(idx + r + 1) * D_;

        float a1 = 0.0f, a2 = 0.0f, c1 = 0.0f, c2 = 0.0f;
#pragma unroll
        for (int c = 0; c < 4; c++) {
            float4 wa = *(const float4*)(rowA + 128 * c + 4 * lane);
            float4 wb = *(const float4*)(rowB + 128 * c + 4 * lane);
            a1 += wa.x * rv1[c].x + wa.y * rv1[c].y + wa.z * rv1[c].z + wa.w * rv1[c].w;
            a2 += wa.x * rv2[c].x + wa.y * rv2[c].y + wa.z * rv2[c].z + wa.w * rv2[c].w;
            c1 += wb.x * rv1[c].x + wb.y * rv1[c].y + wb.z * rv1[c].z + wb.w * rv1[c].w;
            c2 += wb.x * rv2[c].x + wb.y * rv2[c].y + wb.z * rv2[c].z + wb.w * rv2[c].w;
        }
#pragma unroll
        for (int off = 16; off; off >>= 1) {
            a1 += __shfl_xor_sync(0xffffffffu, a1, off);
            a2 += __shfl_xor_sync(0xffffffffu, a2, off);
            c1 += __shfl_xor_sync(0xffffffffu, c1, off);
            c2 += __shfl_xor_sync(0xffffffffu, c2, off);
        }
        a1 *= INV_T; a2 *= INV_T; c1 *= INV_T; c2 *= INV_T;

        // positive logits: global k==0 -> chunk0,r==0; k==KP -> chunk4,r==0
        if (lane == 0 && r == 0 && (chunk == 0 || chunk == NCHUNK / 2)) {
            const int o = (chunk == 0) ? 0 : 2;
            g_pos[b][o + 0] = a1;
            g_pos[b][o + 1] = a2;
        }

        float nm = fmaxf(m1, fmaxf(a1, c1));
        s1 = s1 * __expf(m1 - nm) + __expf(a1 - nm) + __expf(c1 - nm);
        m1 = nm;
        nm = fmaxf(m2, fmaxf(a2, c2));
        s2 = s2 * __expf(m2 - nm) + __expf(a2 - nm) + __expf(c2 - nm);
        m2 = nm;
    }
}

// ---------------------------------------------------------------------------
// Fused kernel, 256 threads, 2 blocks/SM (forced by __launch_bounds__).
// With two blocks resident, most SMs run one copy block AND one loss block
// concurrently: copy saturates the DRAM pipe while loss fills FFMA/L1 issue
// slots -- per-SM overlap instead of per-wave partitioning (the 512-thread
// version pinned each SM to a single role; that was the R8 limiter).
// Role by block id (loss ratio = 1024/5120 = 1/5):
//   blk % 5 == 2 (first 1024 such) -> loss block, loss_id = blk / 5
//   otherwise -> copy block, copy_id = blk - (#loss blocks before blk)
// ---------------------------------------------------------------------------
__global__ void __launch_bounds__(TPB, 2) fused_kernel(const float* __restrict__ v1,
                                                       const float* __restrict__ v2,
                                                       const int*   __restrict__ idx1,
                                                       const int*   __restrict__ idx2,
                                                       const float* __restrict__ mem1,
                                                       const float* __restrict__ mem2,
                                                       float* __restrict__ out)
{
    const int blk = blockIdx.x;
    const bool is_loss = (blk % 5 == 2) && (blk / 5 < LOSS_BLKS);

    // ---------------- copy part ----------------
    if (!is_loss) {
        int nl = (blk + 2) / 5; if (nl > LOSS_BLKS) nl = LOSS_BLKS;
        const int cid = blk - nl;                 // 0..COPY_BLKS-1
        const long long N1 = (long long)NF_ * D_;
        const long long N2 = (long long)NP_ * D_;
        if (cid < COPY_BLKS_1) {
            const long long stride = (long long)COPY_BLKS_1 * TPB;
            const long long tid0 = (long long)cid * TPB + threadIdx.x;
            copy_span<1>(mem1, out + 1, N1, tid0, stride);     // cached: warm L2
        } else {
            const long long stride = (long long)COPY_BLKS_2 * TPB;
            const long long tid0 = (long long)(cid - COPY_BLKS_1) * TPB + threadIdx.x;
            copy_span<0>(mem2, out + 1 + N1, N2, tid0, stride); // streaming
        }
        return;
    }

    // ---------------- loss partial part ----------------
    const int l     = blk / 5;       // 0..1023
    const int b     = l >> 3;        // / NCHUNK
    const int chunk = l & 7;         // % NCHUNK
    const int tid   = threadIdx.x;
    const int warp  = tid >> 5;
    const int lane  = tid & 31;

    __shared__ float sm_m1[NW], sm_s1[NW], sm_m2[NW], sm_s2[NW];

    // v1[b], v2[b] into registers: lane covers d = 128*c + 4*lane + {0..3}
    float4 rv1[4], rv2[4];
#pragma unroll
    for (int c = 0; c < 4; c++) {
        rv1[c] = *(const float4*)(v1 + (size_t)b * D_ + 128 * c + 4 * lane);
        rv2[c] = *(const float4*)(v2 + (size_t)b * D_ + 128 * c + 4 * lane);
    }

    // chunk -> bank and local index base
    const int kbase = chunk * ROWS_PER_CHUNK;          // global k of chunk start
    const bool bank2 = (kbase >= KP_);

    float m1 = -1e30f, s1 = 0.0f;
    float m2 = -1e30f, s2 = 0.0f;

    if (bank2) {
        const int* __restrict__ idx = idx2 + b * KP_ + (kbase - KP_);
        loss_chunk(mem2, idx, rv1, rv2, warp, lane, m1, s1, m2, s2, b, chunk);
    } else {
        const int* __restrict__ idx = idx1 + b * KP_ + kbase;
        loss_chunk(mem1, idx, rv1, rv2, warp, lane, m1, s1, m2, s2, b, chunk);
    }

    if (lane == 0) {
        sm_m1[warp] = m1; sm_s1[warp] = s1;
        sm_m2[warp] = m2; sm_s2[warp] = s2;
    }
    __syncthreads();

    if (tid == 0) {
        float M1 = -1e30f, M2 = -1e30f;
#pragma unroll
        for (int w = 0; w < NW; w++) {
            M1 = fmaxf(M1, sm_m1[w]);
            M2 = fmaxf(M2, sm_m2[w]);
        }
        float S1 = 0.0f, S2 = 0.0f;
#pragma unroll
        for (int w = 0; w < NW; w++) {
            S1 += sm_s1[w] * expf(sm_m1[w] - M1);
            S2 += sm_s2[w] * expf(sm_m2[w] - M2);
        }
        g_m1[b][chunk] = M1; g_s1[b][chunk] = S1;
        g_m2[b][chunk] = M2; g_s2[b][chunk] = S2;
    }
}

// ---------------------------------------------------------------------------
// Kernel 2: momentum row updates (blocks 0..2B-1) + loss finalize (block 2B).
// Duplicate labels: scatter "last update wins".
// ---------------------------------------------------------------------------
__global__ void __launch_bounds__(128) update_kernel(const float* __restrict__ v1,
                                                     const int*   __restrict__ y1,
                                                     const float* __restrict__ v2,
                                                     const int*   __restrict__ y2,
                                                     const float* __restrict__ mem1,
                                                     const float* __restrict__ mem2,
                                                     float* __restrict__ out)
{
    const int blk = blockIdx.x;

    if (blk == 2 * B_) {  // ---- loss finalize: thread b merges chunks ----
        const int tid = threadIdx.x;   // 128 threads, one per b
        float contrib;
        {
            const int b = tid;
            float M1 = -1e30f, M2 = -1e30f;
#pragma unroll
            for (int j = 0; j < NCHUNK; j++) {
                M1 = fmaxf(M1, g_m1[b][j]);
                M2 = fmaxf(M2, g_m2[b][j]);
            }
            float S1 = 0.0f, S2 = 0.0f;
#pragma unroll
            for (int j = 0; j < NCHUNK; j++) {
                S1 += g_s1[b][j] * expf(g_m1[b][j] - M1);
                S2 += g_s2[b][j] * expf(g_m2[b][j] - M2);
            }
            float lse1 = M1 + logf(S1);
            float lse2 = M2 + logf(S2);
            contrib = 0.5f * (g_pos[b][0] + g_pos[b][2]) - lse1
                    + 0.5f * (g_pos[b][1] + g_pos[b][3]) - lse2;
        }
        __shared__ float red[128];
        red[tid] = contrib;
        __syncthreads();
#pragma unroll
        for (int s = 64; s; s >>= 1) {
            if (tid < s) red[tid] += red[tid + s];
            __syncthreads();
        }
        if (tid == 0) out[0] = -red[0] / (2.0f * B_);
        return;
    }

    const int bank = blk / B_;   // 0 -> mem1, 1 -> mem2
    const int b    = blk % B_;

    const int*   __restrict__ y   = bank ? y2 : y1;
    const float* __restrict__ v   = bank ? v2 : v1;
    const float* __restrict__ mem = bank ? mem2 : mem1;
    float* __restrict__ dst = out + 1 + (bank ? (size_t)NF_ * D_ : (size_t)0);

    const int row = __ldg(y + b);
    // last-occurrence-wins: skip if a later b' writes the same row
    for (int b2 = b + 1; b2 < B_; b2++)
        if (__ldg(y + b2) == row) return;   // uniform across block

    const int tid = threadIdx.x;
    float p[4];
    float ss = 0.0f;
#pragma unroll
    for (int j = 0; j < 4; j++) {
        int d = tid + j * 128;
        float x = 0.5f * __ldg(mem + (size_t)row * D_ + d)
                + 0.5f * __ldg(v + (size_t)b * D_ + d);
        p[j] = x;
        ss += x * x;
    }
#pragma unroll
    for (int off = 16; off; off >>= 1)
        ss += __shfl_xor_sync(0xffffffffu, ss, off);

    __shared__ float wsum[4];
    if ((tid & 31) == 0) wsum[tid >> 5] = ss;
    __syncthreads();
    float tot = wsum[0] + wsum[1] + wsum[2] + wsum[3];
    float inv = 1.0f / sqrtf(tot);

#pragma unroll
    for (int j = 0; j < 4; j++) {
        int d = tid + j * 128;
        dst[(size_t)row * D_ + d] = p[j] * inv;
    }
}

// ---------------------------------------------------------------------------
// Launch
// inputs: 0 v1(f32 B*D) 1 y1(i32 B) 2 v2 3 y2 4 idx1(i32 B*KP) 5 idx2
//         6 memory_v1(f32 NF*D) 7 memory_v2(f32 NP*D)
// output: [loss, new_mem_v1 (NF*D), new_mem_v2 (NP*D)]
// ---------------------------------------------------------------------------
extern "C" void kernel_launch(void* const* d_in, const int* in_sizes, int n_in,
                              void* d_out, int out_size)
{
    (void)in_sizes; (void)n_in; (void)out_size;
    const float* v1   = (const float*)d_in[0];
    const int*   y1   = (const int*)  d_in[1];
    const float* v2   = (const float*)d_in[2];
    const int*   y2   = (const int*)  d_in[3];
    const int*   idx1 = (const int*)  d_in[4];
    const int*   idx2 = (const int*)  d_in[5];
    const float* mem1 = (const float*)d_in[6];
    const float* mem2 = (const float*)d_in[7];
    float* out = (float*)d_out;

    fused_kernel<<<TOTAL_BLKS, TPB>>>(v1, v2, idx1, idx2, mem1, mem2, out);
    update_kernel<<<2 * B_ + 1, 128>>>(v1, y1, v2, y2, mem1, mem2, out);
}

// round 15
// speedup vs baseline: 1.1183x; 1.0636x over previous
#include <cuda_runtime.h>

// Problem constants (fixed by the dataset)
#define B_   128
#define D_   512
#define KP_  2048        // K + num_positive
#define NF_  16084
#define NP_  604731
#define INV_T 14.2857142857142857f   // 1 / 0.07

#define NCHUNK 8                      // loss chunks per batch element
#define ROWS_PER_CHUNK (2 * KP_ / NCHUNK)   // 512 rows per chunk

#define COPY_BLKS_1 52
#define COPY_BLKS_2 1996
#define COPY_BLKS   (COPY_BLKS_1 + COPY_BLKS_2)   // 2048
#define LOSS_BLKS   (B_ * NCHUNK)                 // 1024
#define TOTAL_BLKS  (COPY_BLKS + LOSS_BLKS)       // 3072

// Deterministic scratch (no float atomics anywhere)
__device__ float g_m1[B_][NCHUNK], g_s1[B_][NCHUNK];
__device__ float g_m2[B_][NCHUNK], g_s2[B_][NCHUNK];
__device__ float g_pos[B_][4];   // logits at k=0 (t0,t1) and k=KP (t0,t1)

// ---------------------------------------------------------------------------
// Copy span (R8-proven scheme): dst is 4B off 16B alignment (dst = out+1+...).
// Vectorize on the destination: thread covers 4 consecutive dst floats
// starting at j ≡ 3 (mod 4) -> STG.128; the 4 loads per chunk are scalar but
// aggregate-coalesced, each 128B line read exactly once (overlapped vector
// loads + .cs double-read DRAM -- measured R12 regression). 4x unroll.
// SRC_CACHE: 0=streaming (.cs), 1=cached (warm L2 for mem1 gathers).
// Destination stores always streaming (pure write-once traffic).
// ---------------------------------------------------------------------------
template<int SRC_CACHE>
__device__ __forceinline__ void copy_span(const float* __restrict__ src,
                                          float* __restrict__ dst,
                                          long long n,
                                          long long tid0, long long stride)
{
    const long long PRO = 3;
    const long long nv = (n - PRO) >> 2;

    if (tid0 < PRO) dst[tid0] = src[tid0];

#define LD1(J,OFS) (SRC_CACHE ? src[(J)+(OFS)] : __ldcs(src + (J) + (OFS)))

    long long v = tid0;
    for (; v + 3 * stride < nv; v += 4 * stride) {
        const long long j0 = PRO + 4 * v;
        const long long j1 = PRO + 4 * (v + stride);
        const long long j2 = PRO + 4 * (v + 2 * stride);
        const long long j3 = PRO + 4 * (v + 3 * stride);
        float4 r0, r1, r2, r3;
        r0.x = LD1(j0,0); r0.y = LD1(j0,1); r0.z = LD1(j0,2); r0.w = LD1(j0,3);
        r1.x = LD1(j1,0); r1.y = LD1(j1,1); r1.z = LD1(j1,2); r1.w = LD1(j1,3);
        r2.x = LD1(j2,0); r2.y = LD1(j2,1); r2.z = LD1(j2,2); r2.w = LD1(j2,3);
        r3.x = LD1(j3,0); r3.y = LD1(j3,1); r3.z = LD1(j3,2); r3.w = LD1(j3,3);
        __stcs((float4*)(dst + j0), r0);
        __stcs((float4*)(dst + j1), r1);
        __stcs((float4*)(dst + j2), r2);
        __stcs((float4*)(dst + j3), r3);
    }
    for (; v < nv; v += stride) {
        const long long j = PRO + 4 * v;
        float4 r;
        r.x = LD1(j,0); r.y = LD1(j,1); r.z = LD1(j,2); r.w = LD1(j,3);
        __stcs((float4*)(dst + j), r);
    }
#undef LD1

    const long long tail = PRO + 4 * nv;
    const long long t = tail + tid0;
    if (t < n) dst[t] = src[t];
}

// ---------------------------------------------------------------------------
// Fused kernel (R8 configuration -- proven best). Roles INTERLEAVED by block
// id so every scheduling wave carries ~2/3 copy + 1/3 loss work:
//   blk % 3 == 1 -> loss block, loss_id = blk / 3          (1024 blocks)
//   otherwise    -> copy block, copy_id = blk - (blk+2)/3  (2048 blocks)
//
// Loss block (b, chunk): 16 warps; warp w handles rows r = 2*w + 32*i (+1)
// within the chunk's 512 rows; chunk maps wholly to one bank. Lanes keep
// v1[b]/v2[b] in registers; 8 independent LDG.128 + 64 FFMA + 4 interleaved
// butterfly chains per iteration, then online-softmax updates.
// ---------------------------------------------------------------------------
__global__ void __launch_bounds__(512) fused_kernel(const float* __restrict__ v1,
                                                    const float* __restrict__ v2,
                                                    const int*   __restrict__ idx1,
                                                    const int*   __restrict__ idx2,
                                                    const float* __restrict__ mem1,
                                                    const float* __restrict__ mem2,
                                                    float* __restrict__ out)
{
    const int blk = blockIdx.x;
    const bool is_loss = (blk % 3 == 1) && (blk / 3 < LOSS_BLKS);

    // ---------------- copy part ----------------
    if (!is_loss) {
        const int cid = blk - (blk + 2) / 3;     // 0..COPY_BLKS-1
        const long long N1 = (long long)NF_ * D_;
        const long long N2 = (long long)NP_ * D_;
        if (cid < COPY_BLKS_1) {
            const long long stride = (long long)COPY_BLKS_1 * 512;
            const long long tid0 = (long long)cid * 512 + threadIdx.x;
            copy_span<1>(mem1, out + 1, N1, tid0, stride);     // cached: warm L2
        } else {
            const long long stride = (long long)COPY_BLKS_2 * 512;
            const long long tid0 = (long long)(cid - COPY_BLKS_1) * 512 + threadIdx.x;
            copy_span<0>(mem2, out + 1 + N1, N2, tid0, stride); // streaming
        }
        return;
    }

    // ---------------- loss partial part ----------------
    const int l     = blk / 3;       // 0..1023
    const int b     = l >> 3;        // / NCHUNK
    const int chunk = l & 7;         // % NCHUNK
    const int tid   = threadIdx.x;
    const int warp  = tid >> 5;
    const int lane  = tid & 31;
    const int NW    = 16;

    __shared__ float sm_m1[NW], sm_s1[NW], sm_m2[NW], sm_s2[NW];

    // v1[b], v2[b] into registers: lane covers d = 128*c + 4*lane + {0..3}
    float4 rv1[4], rv2[4];
#pragma unroll
    for (int c = 0; c < 4; c++) {
        rv1[c] = *(const float4*)(v1 + (size_t)b * D_ + 128 * c + 4 * lane);
        rv2[c] = *(const float4*)(v2 + (size_t)b * D_ + 128 * c + 4 * lane);
    }

    // chunk -> bank and local index base
    const int kbase = chunk * ROWS_PER_CHUNK;          // global k of chunk start
    const bool bank2 = (kbase >= KP_);
    const float* __restrict__ mem = bank2 ? mem2 : mem1;
    const int* __restrict__ idx = (bank2 ? idx2 + b * KP_ + (kbase - KP_)
                                         : idx1 + b * KP_ + kbase);

    float m1 = -1e30f, s1 = 0.0f;
    float m2 = -1e30f, s2 = 0.0f;

#pragma unroll 1
    for (int r = 2 * warp; r < ROWS_PER_CHUNK; r += 2 * NW) {
        const float* __restrict__ rowA = mem + (size_t)__ldg(idx + r)     * D_;
        const float* __restrict__ rowB = mem + (size_t)__ldg(idx + r + 1) * D_;

        float a1 = 0.0f, a2 = 0.0f, c1 = 0.0f, c2 = 0.0f;
#pragma unroll
        for (int c = 0; c < 4; c++) {
            float4 wa = *(const float4*)(rowA + 128 * c + 4 * lane);
            float4 wb = *(const float4*)(rowB + 128 * c + 4 * lane);
            a1 += wa.x * rv1[c].x + wa.y * rv1[c].y + wa.z * rv1[c].z + wa.w * rv1[c].w;
            a2 += wa.x * rv2[c].x + wa.y * rv2[c].y + wa.z * rv2[c].z + wa.w * rv2[c].w;
            c1 += wb.x * rv1[c].x + wb.y * rv1[c].y + wb.z * rv1[c].z + wb.w * rv1[c].w;
            c2 += wb.x * rv2[c].x + wb.y * rv2[c].y + wb.z * rv2[c].z + wb.w * rv2[c].w;
        }
#pragma unroll
        for (int off = 16; off; off >>= 1) {
            a1 += __shfl_xor_sync(0xffffffffu, a1, off);
            a2 += __shfl_xor_sync(0xffffffffu, a2, off);
            c1 += __shfl_xor_sync(0xffffffffu, c1, off);
            c2 += __shfl_xor_sync(0xffffffffu, c2, off);
        }
        a1 *= INV_T; a2 *= INV_T; c1 *= INV_T; c2 *= INV_T;

        // positive logits: global k==0 -> chunk0,r==0; k==KP -> chunk4,r==0
        if (lane == 0 && r == 0 && (chunk == 0 || chunk == NCHUNK / 2)) {
            const int o = (chunk == 0) ? 0 : 2;
            g_pos[b][o + 0] = a1;
            g_pos[b][o + 1] = a2;
        }

        float nm = fmaxf(m1, fmaxf(a1, c1));
        s1 = s1 * __expf(m1 - nm) + __expf(a1 - nm) + __expf(c1 - nm);
        m1 = nm;
        nm = fmaxf(m2, fmaxf(a2, c2));
        s2 = s2 * __expf(m2 - nm) + __expf(a2 - nm) + __expf(c2 - nm);
        m2 = nm;
    }

    if (lane == 0) {
        sm_m1[warp] = m1; sm_s1[warp] = s1;
        sm_m2[warp] = m2; sm_s2[warp] = s2;
    }
    __syncthreads();

    if (tid == 0) {
        float M1 = -1e30f, M2 = -1e30f;
#pragma unroll
        for (int w = 0; w < NW; w++) {
            M1 = fmaxf(M1, sm_m1[w]);
            M2 = fmaxf(M2, sm_m2[w]);
        }
        float S1 = 0.0f, S2 = 0.0f;
#pragma unroll
        for (int w = 0; w < NW; w++) {
            S1 += sm_s1[w] * expf(sm_m1[w] - M1);
            S2 += sm_s2[w] * expf(sm_m2[w] - M2);
        }
        g_m1[b][chunk] = M1; g_s1[b][chunk] = S1;
        g_m2[b][chunk] = M2; g_s2[b][chunk] = S2;
    }
}

// ---------------------------------------------------------------------------
// Kernel 2: momentum row updates (blocks 0..2B-1) + loss finalize (block 2B).
// Duplicate labels: scatter "last update wins".
// FIX vs R8: the dedup scan previously issued up to 128 dependent global
// loads (~230cyc each -> ~13us kernel). Now the whole y array is loaded into
// smem in ONE coalesced shot (1 LDG/thread) and scanned from smem (~4cyc).
// ---------------------------------------------------------------------------
__global__ void __launch_bounds__(128) update_kernel(const float* __restrict__ v1,
                                                     const int*   __restrict__ y1,
                                                     const float* __restrict__ v2,
                                                     const int*   __restrict__ y2,
                                                     const float* __restrict__ mem1,
                                                     const float* __restrict__ mem2,
                                                     float* __restrict__ out)
{
    const int blk = blockIdx.x;
    const int tid = threadIdx.x;

    if (blk == 2 * B_) {  // ---- loss finalize: thread b merges chunks ----
        float contrib;
        {
            const int b = tid;
            float M1 = -1e30f, M2 = -1e30f;
#pragma unroll
            for (int j = 0; j < NCHUNK; j++) {
                M1 = fmaxf(M1, g_m1[b][j]);
                M2 = fmaxf(M2, g_m2[b][j]);
            }
            float S1 = 0.0f, S2 = 0.0f;
#pragma unroll
            for (int j = 0; j < NCHUNK; j++) {
                S1 += g_s1[b][j] * expf(g_m1[b][j] - M1);
                S2 += g_s2[b][j] * expf(g_m2[b][j] - M2);
            }
            float lse1 = M1 + logf(S1);
            float lse2 = M2 + logf(S2);
            contrib = 0.5f * (g_pos[b][0] + g_pos[b][2]) - lse1
                    + 0.5f * (g_pos[b][1] + g_pos[b][3]) - lse2;
        }
        __shared__ float red[128];
        red[tid] = contrib;
        __syncthreads();
#pragma unroll
        for (int s = 64; s; s >>= 1) {
            if (tid < s) red[tid] += red[tid + s];
            __syncthreads();
        }
        if (tid == 0) out[0] = -red[0] / (2.0f * B_);
        return;
    }

    const int bank = blk / B_;   // 0 -> mem1, 1 -> mem2
    const int b    = blk % B_;

    const int*   __restrict__ y   = bank ? y2 : y1;
    const float* __restrict__ v   = bank ? v2 : v1;
    const float* __restrict__ mem = bank ? mem2 : mem1;
    float* __restrict__ dst = out + 1 + (bank ? (size_t)NF_ * D_ : (size_t)0);

    // coalesced y load into smem, then fast dedup scan
    __shared__ int sy[B_];
    sy[tid] = __ldg(y + tid);     // blockDim == B_ == 128
    __syncthreads();

    const int row = sy[b];
    // last-occurrence-wins: skip if a later b' writes the same row
    bool dup = false;
#pragma unroll 4
    for (int b2 = b + 1; b2 < B_; b2++)
        dup |= (sy[b2] == row);
    if (dup) return;              // uniform across block

    float p[4];
    float ss = 0.0f;
#pragma unroll
    for (int j = 0; j < 4; j++) {
        int d = tid + j * 128;
        float x = 0.5f * __ldg(mem + (size_t)row * D_ + d)
                + 0.5f * __ldg(v + (size_t)b * D_ + d);
        p[j] = x;
        ss += x * x;
    }
#pragma unroll
    for (int off = 16; off; off >>= 1)
        ss += __shfl_xor_sync(0xffffffffu, ss, off);

    __shared__ float wsum[4];
    if ((tid & 31) == 0) wsum[tid >> 5] = ss;
    __syncthreads();
    float tot = wsum[0] + wsum[1] + wsum[2] + wsum[3];
    float inv = 1.0f / sqrtf(tot);

#pragma unroll
    for (int j = 0; j < 4; j++) {
        int d = tid + j * 128;
        dst[(size_t)row * D_ + d] = p[j] * inv;
    }
}

// ---------------------------------------------------------------------------
// Launch
// inputs: 0 v1(f32 B*D) 1 y1(i32 B) 2 v2 3 y2 4 idx1(i32 B*KP) 5 idx2
//         6 memory_v1(f32 NF*D) 7 memory_v2(f32 NP*D)
// output: [loss, new_mem_v1 (NF*D), new_mem_v2 (NP*D)]
// ---------------------------------------------------------------------------
extern "C" void kernel_launch(void* const* d_in, const int* in_sizes, int n_in,
                              void* d_out, int out_size)
{
    (void)in_sizes; (void)n_in; (void)out_size;
    const float* v1   = (const float*)d_in[0];
    const int*   y1   = (const int*)  d_in[1];
    const float* v2   = (const float*)d_in[2];
    const int*   y2   = (const int*)  d_in[3];
    const int*   idx1 = (const int*)  d_in[4];
    const int*   idx2 = (const int*)  d_in[5];
    const float* mem1 = (const float*)d_in[6];
    const float* mem2 = (const float*)d_in[7];
    float* out = (float*)d_out;

    fused_kernel<<<TOTAL_BLKS, 512>>>(v1, v2, idx1, idx2, mem1, mem2, out);
    update_kernel<<<2 * B_ + 1, 128>>>(v1, y1, v2, y2, mem1, mem2, out);
}